// round 13
// baseline (speedup 1.0000x reference)
#include <cuda_runtime.h>
#include <cuda_fp16.h>
#include <cstdint>

typedef uint32_t u32;

// ------------------------------------------------------------------
// LISTA fused, mma.sync f16 (m16n8k16, fp32 accum), round 13.
//   B    = We @ x        (computed once, stored fp16 in smem)
//   z    = softshrink(B, th0)
//   3x:  z = softshrink(S[i] @ z + B, th[i+1])
//
// CTA = 64 px x 256 dict, 256 threads = 8 warps (4 dict x 2 px),
// warp tile 64d x 32px, 2 CTAs/SM.
// A (weight) fragments: cp.async into a PER-WD-PAIR 2-slot smem ring,
// synced with per-pair named barriers (bar.sync 1+wd, 64) -- no
// CTA-wide barriers in the chunk loop, full-chunk prefetch lead so
// L2 latency is never exposed. z in smem (k-pair half2, XOR swizzle);
// B in smem fp16 per-thread order. 26 chunks of K=32.
// ------------------------------------------------------------------

// smem u32-word map:
//   [0,     8192)  z: 128 pair-rows x 64 px (half2)
//   [8192, 16384)  setup: x (32 pair-rows x 64) ; after GEMM0: B (fp16)
//   [16384, 24576) A-ring: 4 wd x 2 slots x 1024 words
#define BS_OFF     8192
#define A_OFF      16384
#define SMEM_BYTES (24576 * 4)           // 98304 -> 2 CTAs/SM
#define N_CHUNKS   26                    // 2 We + 24 S, each K=32
#define WBUF_WORDS 4096

__device__ __align__(16) u32 g_wfrag[N_CHUNKS * WBUF_WORDS];

__device__ __forceinline__ u32 smem_u32(const void* p) {
    u32 a;
    asm("{ .reg .u64 t; cvta.to.shared.u64 t, %1; cvt.u32.u64 %0, t; }"
        : "=r"(a) : "l"(p));
    return a;
}
__device__ __forceinline__ float sshrink(float f, float th) {
    return f - fminf(fmaxf(f, -th), th);
}
__device__ __forceinline__ void mma16(float* c, const u32* a, u32 b0, u32 b1) {
    asm volatile(
        "mma.sync.aligned.m16n8k16.row.col.f32.f16.f16.f32 "
        "{%0,%1,%2,%3}, {%4,%5,%6,%7}, {%8,%9}, {%0,%1,%2,%3};"
        : "+f"(c[0]), "+f"(c[1]), "+f"(c[2]), "+f"(c[3])
        : "r"(a[0]), "r"(a[1]), "r"(a[2]), "r"(a[3]), "r"(b0), "r"(b1));
}
__device__ __forceinline__ void lds128(u32* r, u32 addr) {
    asm volatile("ld.shared.v4.b32 {%0,%1,%2,%3}, [%4];"
                 : "=r"(r[0]), "=r"(r[1]), "=r"(r[2]), "=r"(r[3]) : "r"(addr));
}

// warp stages ITS half (wp) of chunk i's wd-block into ring slot s
__device__ __forceinline__ void stage_pair(u32 smb, int i, int s,
                                           int wd, int wp, int lane)
{
    const u32* src = g_wfrag + (size_t)i * WBUF_WORDS + wd * 1024
                     + wp * 512 + lane * 4;
    const u32 dst = smb + (u32)(A_OFF + (wd * 2 + s) * 1024
                     + wp * 512 + lane * 4) * 4;
#pragma unroll
    for (int e = 0; e < 4; e++)
        asm volatile("cp.async.ca.shared.global [%0], [%1], 16;"
                     :: "r"(dst + (u32)(e * 512)), "l"(src + e * 128)
                     : "memory");
    asm volatile("cp.async.commit_group;" ::: "memory");
}

// ------------- prep: pack We/S into fp16 a-fragment order -------------
// word layout per K=32 chunk (4096 words): [wd 2][step 1][mt 2][lane 5][reg 2]
//   d = wd*64 + mt*16 + (reg&1)*8 + (lane>>2)
//   k = step*16 + (reg>>1)*8 + (lane&3)*2  (+0,+1 packed)
// chunk order = execution order: 0,1 = We k[0:32),k[32:64); 2.. = S.
__global__ void __launch_bounds__(256, 4)
lista_prep(const float* __restrict__ We, const float* __restrict__ S)
{
    const int w = blockIdx.x * 256 + threadIdx.x;
    if (w >= N_CHUNKS * WBUF_WORDS) return;
    const int chunk = w >> 12;
    const int rem   = w & 4095;
    const int wd    = rem >> 10;
    const int step  = (rem >> 9) & 1;
    const int mt    = (rem >> 7) & 3;
    const int lane  = (rem >> 2) & 31;
    const int reg   = rem & 3;
    const int d = wd * 64 + mt * 16 + (reg & 1) * 8 + (lane >> 2);
    const int k = step * 16 + (reg >> 1) * 8 + (lane & 3) * 2;
    float v0, v1;
    if (chunk < 2) {
        v0 = We[d * 64 + chunk * 32 + k];
        v1 = We[d * 64 + chunk * 32 + k + 1];
    } else {
        const int c = chunk - 2, g = c >> 3, j = c & 7;
        v0 = S[g * 65536 + d * 256 + j * 32 + k];
        v1 = S[g * 65536 + d * 256 + j * 32 + k + 1];
    }
    __half2 h = __floats2half2_rn(v0, v1);
    g_wfrag[w] = *reinterpret_cast<u32*>(&h);
}

// ---------------- main fused kernel ----------------
__global__ void __launch_bounds__(256, 2)
lista_main(const float* __restrict__ x,
           const float* __restrict__ th,
           float* __restrict__ out)
{
    extern __shared__ u32 smem[];
    u32* Zkp = smem;

    const int tid  = threadIdx.x;
    const int lane = tid & 31;
    const int wid  = tid >> 5;
    const int wd   = wid & 3;               // dict group (64 d)
    const int wp   = wid >> 2;              // pixel group (32 px), 0..1
    const int r    = lane >> 2;
    const int c    = lane & 3;

    const int pix0 = blockIdx.x * 64;
    const int b    = pix0 >> 16;            // 65536 px per image
    const int hw0  = pix0 & 65535;

    const u32 smb = smem_u32(smem);
    const int bid = 1 + wd;                 // named barrier id for this pair

    // prologue: stage chunks 0 (slot 0) and 1 (slot 1)
    stage_pair(smb, 0, 0, wd, wp, lane);
    stage_pair(smb, 1, 1, wd, wp, lane);

    const float th0 = __ldg(th + 0), th1 = __ldg(th + 1);
    const float th2 = __ldg(th + 2), th3 = __ldg(th + 3);

    // ---- stage x into pair-rows 0..31 of the B region (XOR swizzle) ----
    {
        const float* xb = x + (size_t)b * 64 * 65536 + hw0;
#pragma unroll
        for (int e = 0; e < 8; e++) {
            const int idx = tid + e * 256;          // 2048 = 32 prow * 64 px
            const int px  = idx & 63;
            const int pr  = idx >> 6;               // 0..31
            const float v0 = __ldg(xb + (size_t)(2 * pr) * 65536 + px);
            const float v1 = __ldg(xb + (size_t)(2 * pr + 1) * 65536 + px);
            __half2 h = __floats2half2_rn(v0, v1);
            Zkp[BS_OFF + pr * 64 + (px ^ ((pr & 3) << 3))] =
                *reinterpret_cast<u32*>(&h);
        }
    }
    __syncthreads();                        // x visible to all warps

    float acc[4][4][4];
#pragma unroll
    for (int mt = 0; mt < 4; mt++)
#pragma unroll
        for (int nt = 0; nt < 4; nt++)
#pragma unroll
            for (int q = 0; q < 4; q++) acc[mt][nt][q] = 0.0f;

    const int nb = wp * 32 + r;

#pragma unroll 1
    for (int i = 0; i < N_CHUNKS; i++) {
        // one group per chunk -> wait_group 1 guarantees chunk i's data landed
        asm volatile("cp.async.wait_group 1;" ::: "memory");
        asm volatile("bar.sync %0, 64;" :: "r"(bid) : "memory");  // pair ready

        const u32* zbase = (i < 2) ? (Zkp + BS_OFF) : Zkp;   // We chunks read x
        const int  kpb   = (i < 2) ? i * 16 : ((i - 2) & 7) * 16;
        const u32 abase  = smb + (u32)(A_OFF + (wd * 2 + (i & 1)) * 1024
                           + lane * 4) * 4;

#pragma unroll
        for (int step = 0; step < 2; step++) {
            u32 a[4][4];
#pragma unroll
            for (int mt = 0; mt < 4; mt++)
                lds128(a[mt], abase + (u32)((step * 512 + mt * 128) * 4));
            const u32* zrow = zbase + (kpb + step * 8 + c) * 64;
            u32 bf[4][2];
#pragma unroll
            for (int nt = 0; nt < 4; nt++) {
                const int col = nb + (((nt ^ c) & 3) << 3);
                bf[nt][0] = zrow[col];
                bf[nt][1] = zrow[4 * 64 + col];
            }
#pragma unroll
            for (int mt = 0; mt < 4; mt++)
#pragma unroll
                for (int nt = 0; nt < 4; nt++)
                    mma16(acc[mt][nt], a[mt], bf[nt][0], bf[nt][1]);
        }

        // pair done reading slot i&1 -> safe to restage it
        asm volatile("bar.sync %0, 64;" :: "r"(bid) : "memory");
        if (i + 2 < N_CHUNKS)
            stage_pair(smb, i + 2, i & 1, wd, wp, lane);
        else
            asm volatile("cp.async.commit_group;" ::: "memory"); // keep count

        // ---- iteration-boundary epilogues ----
        if (i == 1) {
            __syncthreads();    // all x reads done before B overwrites region
            const bool odd = (r & 1);
#pragma unroll
            for (int mt = 0; mt < 4; mt++) {
                const int prow_lo = wd * 32 + mt * 8 + (r >> 1);
                const int prow    = odd ? (prow_lo + 4) : prow_lo;
                const int swz     = (prow & 3) << 3;
#pragma unroll
                for (int nt = 0; nt < 4; nt++) {
                    __half2 hb0 = __floats2half2_rn(acc[mt][nt][0], acc[mt][nt][1]);
                    __half2 hb1 = __floats2half2_rn(acc[mt][nt][2], acc[mt][nt][3]);
                    const int wB = (mt * 4 + nt) * 2;
                    Zkp[BS_OFF + wB * 256 + tid]       = *reinterpret_cast<u32*>(&hb0);
                    Zkp[BS_OFF + (wB + 1) * 256 + tid] = *reinterpret_cast<u32*>(&hb1);
                    const float s0 = sshrink(acc[mt][nt][0], th0);
                    const float s1 = sshrink(acc[mt][nt][1], th0);
                    const float s2 = sshrink(acc[mt][nt][2], th0);
                    const float s3 = sshrink(acc[mt][nt][3], th0);
                    const float o0 = __shfl_xor_sync(0xffffffffu, s0, 4);
                    const float o1 = __shfl_xor_sync(0xffffffffu, s1, 4);
                    const float o2 = __shfl_xor_sync(0xffffffffu, s2, 4);
                    const float o3 = __shfl_xor_sync(0xffffffffu, s3, 4);
                    __half2 h0, h1;
                    if (!odd) { h0 = __floats2half2_rn(s0, o0);
                                h1 = __floats2half2_rn(s1, o1); }
                    else      { h0 = __floats2half2_rn(o2, s2);
                                h1 = __floats2half2_rn(o3, s3); }
                    const int col = (wp * 32 + nt * 8 + 2 * c) ^ swz;
                    uint2 v;
                    v.x = *reinterpret_cast<u32*>(&h0);
                    v.y = *reinterpret_cast<u32*>(&h1);
                    *reinterpret_cast<uint2*>(Zkp + prow * 64 + col) = v;
                    acc[mt][nt][0] = 0.0f; acc[mt][nt][1] = 0.0f;
                    acc[mt][nt][2] = 0.0f; acc[mt][nt][3] = 0.0f;
                }
            }
            __syncthreads();    // z0 / B visible before next chunk reads
        } else if (i == 9 || i == 17) {
            __syncthreads();    // all z reads of this iteration done
            const float theta = (i == 9) ? th1 : th2;
            const bool odd = (r & 1);
#pragma unroll
            for (int mt = 0; mt < 4; mt++) {
                const int prow_lo = wd * 32 + mt * 8 + (r >> 1);
                const int prow    = odd ? (prow_lo + 4) : prow_lo;
                const int swz     = (prow & 3) << 3;
#pragma unroll
                for (int nt = 0; nt < 4; nt++) {
                    const int wB = (mt * 4 + nt) * 2;
                    const u32 bw0 = Zkp[BS_OFF + wB * 256 + tid];
                    const u32 bw1 = Zkp[BS_OFF + (wB + 1) * 256 + tid];
                    const float2 b0 =
                        __half22float2(*reinterpret_cast<const __half2*>(&bw0));
                    const float2 b1 =
                        __half22float2(*reinterpret_cast<const __half2*>(&bw1));
                    const float s0 = sshrink(acc[mt][nt][0] + b0.x, theta);
                    const float s1 = sshrink(acc[mt][nt][1] + b0.y, theta);
                    const float s2 = sshrink(acc[mt][nt][2] + b1.x, theta);
                    const float s3 = sshrink(acc[mt][nt][3] + b1.y, theta);
                    const float o0 = __shfl_xor_sync(0xffffffffu, s0, 4);
                    const float o1 = __shfl_xor_sync(0xffffffffu, s1, 4);
                    const float o2 = __shfl_xor_sync(0xffffffffu, s2, 4);
                    const float o3 = __shfl_xor_sync(0xffffffffu, s3, 4);
                    __half2 h0, h1;
                    if (!odd) { h0 = __floats2half2_rn(s0, o0);
                                h1 = __floats2half2_rn(s1, o1); }
                    else      { h0 = __floats2half2_rn(o2, s2);
                                h1 = __floats2half2_rn(o3, s3); }
                    const int col = (wp * 32 + nt * 8 + 2 * c) ^ swz;
                    uint2 v;
                    v.x = *reinterpret_cast<u32*>(&h0);
                    v.y = *reinterpret_cast<u32*>(&h1);
                    *reinterpret_cast<uint2*>(Zkp + prow * 64 + col) = v;
                    acc[mt][nt][0] = 0.0f; acc[mt][nt][1] = 0.0f;
                    acc[mt][nt][2] = 0.0f; acc[mt][nt][3] = 0.0f;
                }
            }
            __syncthreads();    // new z visible before next chunk reads
        }
    }

    // ---- final epilogue: out = softshrink(acc + B, th3) -> gmem ----
    {
        float* ob = out + (size_t)b * 256 * 65536 + hw0;
#pragma unroll
        for (int mt = 0; mt < 4; mt++) {
            const int d0 = wd * 64 + mt * 16 + r;
#pragma unroll
            for (int nt = 0; nt < 4; nt++) {
                const int wB = (mt * 4 + nt) * 2;
                const u32 bw0 = Zkp[BS_OFF + wB * 256 + tid];
                const u32 bw1 = Zkp[BS_OFF + (wB + 1) * 256 + tid];
                const float2 b0 =
                    __half22float2(*reinterpret_cast<const __half2*>(&bw0));
                const float2 b1 =
                    __half22float2(*reinterpret_cast<const __half2*>(&bw1));
                const int px0 = wp * 32 + nt * 8 + 2 * c;
                *reinterpret_cast<float2*>(ob + (size_t)d0 * 65536 + px0) =
                    make_float2(sshrink(acc[mt][nt][0] + b0.x, th3),
                                sshrink(acc[mt][nt][1] + b0.y, th3));
                *reinterpret_cast<float2*>(ob + (size_t)(d0 + 8) * 65536 + px0) =
                    make_float2(sshrink(acc[mt][nt][2] + b1.x, th3),
                                sshrink(acc[mt][nt][3] + b1.y, th3));
            }
        }
    }
}

extern "C" void kernel_launch(void* const* d_in, const int* in_sizes, int n_in,
                              void* d_out, int out_size)
{
    (void)in_sizes; (void)n_in; (void)out_size;
    const float* x  = (const float*)d_in[0];
    const float* We = (const float*)d_in[1];
    const float* S  = (const float*)d_in[2];
    const float* th = (const float*)d_in[3];
    float* out      = (float*)d_out;

    lista_prep<<<(N_CHUNKS * WBUF_WORDS + 255) / 256, 256>>>(We, S);

    cudaFuncSetAttribute(lista_main, cudaFuncAttributeMaxDynamicSharedMemorySize,
                         SMEM_BYTES);
    lista_main<<<4096, 256, SMEM_BYTES>>>(x, th, out);
}

// round 14
// speedup vs baseline: 1.0988x; 1.0988x over previous
#include <cuda_runtime.h>
#include <cuda_fp16.h>
#include <cstdint>

typedef uint32_t u32;

// ------------------------------------------------------------------
// LISTA fused, mma.sync f16 (m16n8k16, fp32 accum), round 14.
//  = round 12 (best: 334us) + L1 prefetch of next chunk's A-fragments.
//   B    = We @ x        (computed once, stored fp16 in smem)
//   z    = softshrink(B, th0)
//   3x:  z = softshrink(S[i] @ z + B, th[i+1])
//
// CTA = 64 px x 256 dict, 256 threads = 8 warps (4 dict x 2 px),
// warp tile 64d x 32px, 2 CTAs/SM.
// A (weight) fragments: pre-packed in gmem fragment order, loaded
// directly gmem->registers (ld.global.nc.v4) with one-step-ahead
// register prefetch AND one-chunk-ahead prefetch.global.L1 so the
// LDGs hit L1 (~39cyc) instead of L2 (~234cyc).
// z in smem (k-pair half2, XOR swizzle); B in smem fp16 per-thread.
// ------------------------------------------------------------------

// smem u32-word map:
//   [0,    8192)  z: 128 pair-rows x 64 px (half2)
//   [8192,16384)  setup: x (32 pair-rows x 64) ; after GEMM0: B (fp16)
#define BS_OFF     8192
#define SMEM_BYTES (16384 * 4)           // 65536
#define N_CHUNKS   26                    // 2 We + 24 S, each K=32
#define WBUF_WORDS 4096

__device__ __align__(16) u32 g_wfrag[N_CHUNKS * WBUF_WORDS];

__device__ __forceinline__ float sshrink(float f, float th) {
    return f - fminf(fmaxf(f, -th), th);
}
__device__ __forceinline__ void mma16(float* c, const u32* a, u32 b0, u32 b1) {
    asm volatile(
        "mma.sync.aligned.m16n8k16.row.col.f32.f16.f16.f32 "
        "{%0,%1,%2,%3}, {%4,%5,%6,%7}, {%8,%9}, {%0,%1,%2,%3};"
        : "+f"(c[0]), "+f"(c[1]), "+f"(c[2]), "+f"(c[3])
        : "r"(a[0]), "r"(a[1]), "r"(a[2]), "r"(a[3]), "r"(b0), "r"(b1));
}
__device__ __forceinline__ void ldg4(u32* r, const u32* p) {
    asm volatile("ld.global.nc.v4.u32 {%0,%1,%2,%3}, [%4];"
                 : "=r"(r[0]), "=r"(r[1]), "=r"(r[2]), "=r"(r[3]) : "l"(p));
}
__device__ __forceinline__ void pf_l1(const u32* p) {
    asm volatile("prefetch.global.L1 [%0];" :: "l"(p));
}

// ------------- prep: pack We/S into fp16 a-fragment order -------------
// word layout per K=32 chunk (4096 words): [wd 2][step 1][mt 2][lane 5][reg 2]
//   d = wd*64 + mt*16 + (reg&1)*8 + (lane>>2)
//   k = step*16 + (reg>>1)*8 + (lane&3)*2  (+0,+1 packed)
// chunk order = execution order: 0,1 = We k[0:32),k[32:64); 2.. = S.
__global__ void __launch_bounds__(256, 4)
lista_prep(const float* __restrict__ We, const float* __restrict__ S)
{
    const int w = blockIdx.x * 256 + threadIdx.x;
    if (w >= N_CHUNKS * WBUF_WORDS) return;
    const int chunk = w >> 12;
    const int rem   = w & 4095;
    const int wd    = rem >> 10;
    const int step  = (rem >> 9) & 1;
    const int mt    = (rem >> 7) & 3;
    const int lane  = (rem >> 2) & 31;
    const int reg   = rem & 3;
    const int d = wd * 64 + mt * 16 + (reg & 1) * 8 + (lane >> 2);
    const int k = step * 16 + (reg >> 1) * 8 + (lane & 3) * 2;
    float v0, v1;
    if (chunk < 2) {
        v0 = We[d * 64 + chunk * 32 + k];
        v1 = We[d * 64 + chunk * 32 + k + 1];
    } else {
        const int c = chunk - 2, g = c >> 3, j = c & 7;
        v0 = S[g * 65536 + d * 256 + j * 32 + k];
        v1 = S[g * 65536 + d * 256 + j * 32 + k + 1];
    }
    __half2 h = __floats2half2_rn(v0, v1);
    g_wfrag[w] = *reinterpret_cast<u32*>(&h);
}

// ---------------- main fused kernel ----------------
__global__ void __launch_bounds__(256, 2)
lista_main(const float* __restrict__ x,
           const float* __restrict__ th,
           float* __restrict__ out)
{
    extern __shared__ u32 smem[];
    u32* Zkp = smem;

    const int tid  = threadIdx.x;
    const int lane = tid & 31;
    const int wid  = tid >> 5;
    const int wd   = wid & 3;               // dict group (64 d)
    const int wp   = wid >> 2;              // pixel group (32 px), 0..1
    const int r    = lane >> 2;
    const int c    = lane & 3;

    const int pix0 = blockIdx.x * 64;
    const int b    = pix0 >> 16;            // 65536 px per image
    const int hw0  = pix0 & 65535;

    const float th0 = __ldg(th + 0), th1 = __ldg(th + 1);
    const float th2 = __ldg(th + 2), th3 = __ldg(th + 3);

    // per-warp fragment base in gmem: [wd][step][mt][lane][reg]
    const u32* gw = g_wfrag + (wd * 2) * 512 + lane * 4;
    // per-warp 4KB block base (for L1 prefetch): lane covers one 128B line
    const u32* gpf = g_wfrag + wd * 1024 + lane * 32;

    // prefetch chunk 0, step 0 fragments
    u32 a0[16], a1[16];
#pragma unroll
    for (int mt = 0; mt < 4; mt++) ldg4(a0 + 4 * mt, gw + mt * 128);
    pf_l1(gpf);                              // rest of chunk 0 into L1
    pf_l1(gpf + WBUF_WORDS);                 // chunk 1 into L1

    // ---- stage x into pair-rows 0..31 of the B region (XOR swizzle) ----
    {
        const float* xb = x + (size_t)b * 64 * 65536 + hw0;
#pragma unroll
        for (int e = 0; e < 8; e++) {
            const int idx = tid + e * 256;          // 2048 = 32 prow * 64 px
            const int px  = idx & 63;
            const int pr  = idx >> 6;               // 0..31
            const float v0 = __ldg(xb + (size_t)(2 * pr) * 65536 + px);
            const float v1 = __ldg(xb + (size_t)(2 * pr + 1) * 65536 + px);
            __half2 h = __floats2half2_rn(v0, v1);
            Zkp[BS_OFF + pr * 64 + (px ^ ((pr & 3) << 3))] =
                *reinterpret_cast<u32*>(&h);
        }
    }
    __syncthreads();                        // x visible to all warps

    float acc[4][4][4];
#pragma unroll
    for (int mt = 0; mt < 4; mt++)
#pragma unroll
        for (int nt = 0; nt < 4; nt++)
#pragma unroll
            for (int q = 0; q < 4; q++) acc[mt][nt][q] = 0.0f;

    const int nb = wp * 32 + r;

#pragma unroll 1
    for (int i = 0; i < N_CHUNKS; i++) {
        const u32* zbase = (i < 2) ? (Zkp + BS_OFF) : Zkp;   // We chunks read x
        const int  kpb   = (i < 2) ? i * 16 : ((i - 2) & 7) * 16;
        const u32* gwc   = gw + (size_t)i * WBUF_WORDS;

        // L1-prefetch chunk i+2's whole 4KB block (one line per lane)
        if (i + 2 < N_CHUNKS)
            pf_l1(gpf + (size_t)(i + 2) * WBUF_WORDS);

        // load step-1 fragments (consumed after step-0 MMAs)
#pragma unroll
        for (int mt = 0; mt < 4; mt++) ldg4(a1 + 4 * mt, gwc + 512 + mt * 128);

        // ---- step 0 ----
        {
            const u32* zrow = zbase + (kpb + c) * 64;
            u32 bf[4][2];
#pragma unroll
            for (int nt = 0; nt < 4; nt++) {
                const int col = nb + (((nt ^ c) & 3) << 3);
                bf[nt][0] = zrow[col];
                bf[nt][1] = zrow[4 * 64 + col];
            }
#pragma unroll
            for (int mt = 0; mt < 4; mt++)
#pragma unroll
                for (int nt = 0; nt < 4; nt++)
                    mma16(acc[mt][nt], a0 + 4 * mt, bf[nt][0], bf[nt][1]);
        }

        // prefetch next chunk's step-0 fragments
        if (i + 1 < N_CHUNKS) {
#pragma unroll
            for (int mt = 0; mt < 4; mt++)
                ldg4(a0 + 4 * mt, gwc + WBUF_WORDS + mt * 128);
        }

        // ---- step 1 ----
        {
            const u32* zrow = zbase + (kpb + 8 + c) * 64;
            u32 bf[4][2];
#pragma unroll
            for (int nt = 0; nt < 4; nt++) {
                const int col = nb + (((nt ^ c) & 3) << 3);
                bf[nt][0] = zrow[col];
                bf[nt][1] = zrow[4 * 64 + col];
            }
#pragma unroll
            for (int mt = 0; mt < 4; mt++)
#pragma unroll
                for (int nt = 0; nt < 4; nt++)
                    mma16(acc[mt][nt], a1 + 4 * mt, bf[nt][0], bf[nt][1]);
        }

        // ---- iteration-boundary epilogues ----
        if (i == 1) {
            __syncthreads();    // all x reads done before B overwrites region
            const bool odd = (r & 1);
#pragma unroll
            for (int mt = 0; mt < 4; mt++) {
                const int prow_lo = wd * 32 + mt * 8 + (r >> 1);
                const int prow    = odd ? (prow_lo + 4) : prow_lo;
                const int swz     = (prow & 3) << 3;
#pragma unroll
                for (int nt = 0; nt < 4; nt++) {
                    __half2 hb0 = __floats2half2_rn(acc[mt][nt][0], acc[mt][nt][1]);
                    __half2 hb1 = __floats2half2_rn(acc[mt][nt][2], acc[mt][nt][3]);
                    const int wB = (mt * 4 + nt) * 2;
                    Zkp[BS_OFF + wB * 256 + tid]       = *reinterpret_cast<u32*>(&hb0);
                    Zkp[BS_OFF + (wB + 1) * 256 + tid] = *reinterpret_cast<u32*>(&hb1);
                    const float s0 = sshrink(acc[mt][nt][0], th0);
                    const float s1 = sshrink(acc[mt][nt][1], th0);
                    const float s2 = sshrink(acc[mt][nt][2], th0);
                    const float s3 = sshrink(acc[mt][nt][3], th0);
                    const float o0 = __shfl_xor_sync(0xffffffffu, s0, 4);
                    const float o1 = __shfl_xor_sync(0xffffffffu, s1, 4);
                    const float o2 = __shfl_xor_sync(0xffffffffu, s2, 4);
                    const float o3 = __shfl_xor_sync(0xffffffffu, s3, 4);
                    __half2 h0, h1;
                    if (!odd) { h0 = __floats2half2_rn(s0, o0);
                                h1 = __floats2half2_rn(s1, o1); }
                    else      { h0 = __floats2half2_rn(o2, s2);
                                h1 = __floats2half2_rn(o3, s3); }
                    const int col = (wp * 32 + nt * 8 + 2 * c) ^ swz;
                    uint2 v;
                    v.x = *reinterpret_cast<u32*>(&h0);
                    v.y = *reinterpret_cast<u32*>(&h1);
                    *reinterpret_cast<uint2*>(Zkp + prow * 64 + col) = v;
                    acc[mt][nt][0] = 0.0f; acc[mt][nt][1] = 0.0f;
                    acc[mt][nt][2] = 0.0f; acc[mt][nt][3] = 0.0f;
                }
            }
            __syncthreads();    // z0 / B visible before next chunk reads
        } else if (i == 9 || i == 17) {
            __syncthreads();    // all z reads of this iteration done
            const float theta = (i == 9) ? th1 : th2;
            const bool odd = (r & 1);
#pragma unroll
            for (int mt = 0; mt < 4; mt++) {
                const int prow_lo = wd * 32 + mt * 8 + (r >> 1);
                const int prow    = odd ? (prow_lo + 4) : prow_lo;
                const int swz     = (prow & 3) << 3;
#pragma unroll
                for (int nt = 0; nt < 4; nt++) {
                    const int wB = (mt * 4 + nt) * 2;
                    const u32 bw0 = Zkp[BS_OFF + wB * 256 + tid];
                    const u32 bw1 = Zkp[BS_OFF + (wB + 1) * 256 + tid];
                    const float2 b0 =
                        __half22float2(*reinterpret_cast<const __half2*>(&bw0));
                    const float2 b1 =
                        __half22float2(*reinterpret_cast<const __half2*>(&bw1));
                    const float s0 = sshrink(acc[mt][nt][0] + b0.x, theta);
                    const float s1 = sshrink(acc[mt][nt][1] + b0.y, theta);
                    const float s2 = sshrink(acc[mt][nt][2] + b1.x, theta);
                    const float s3 = sshrink(acc[mt][nt][3] + b1.y, theta);
                    const float o0 = __shfl_xor_sync(0xffffffffu, s0, 4);
                    const float o1 = __shfl_xor_sync(0xffffffffu, s1, 4);
                    const float o2 = __shfl_xor_sync(0xffffffffu, s2, 4);
                    const float o3 = __shfl_xor_sync(0xffffffffu, s3, 4);
                    __half2 h0, h1;
                    if (!odd) { h0 = __floats2half2_rn(s0, o0);
                                h1 = __floats2half2_rn(s1, o1); }
                    else      { h0 = __floats2half2_rn(o2, s2);
                                h1 = __floats2half2_rn(o3, s3); }
                    const int col = (wp * 32 + nt * 8 + 2 * c) ^ swz;
                    uint2 v;
                    v.x = *reinterpret_cast<u32*>(&h0);
                    v.y = *reinterpret_cast<u32*>(&h1);
                    *reinterpret_cast<uint2*>(Zkp + prow * 64 + col) = v;
                    acc[mt][nt][0] = 0.0f; acc[mt][nt][1] = 0.0f;
                    acc[mt][nt][2] = 0.0f; acc[mt][nt][3] = 0.0f;
                }
            }
            __syncthreads();    // new z visible before next chunk reads
        }
    }

    // ---- final epilogue: out = softshrink(acc + B, th3) -> gmem ----
    {
        float* ob = out + (size_t)b * 256 * 65536 + hw0;
#pragma unroll
        for (int mt = 0; mt < 4; mt++) {
            const int d0 = wd * 64 + mt * 16 + r;
#pragma unroll
            for (int nt = 0; nt < 4; nt++) {
                const int wB = (mt * 4 + nt) * 2;
                const u32 bw0 = Zkp[BS_OFF + wB * 256 + tid];
                const u32 bw1 = Zkp[BS_OFF + (wB + 1) * 256 + tid];
                const float2 b0 =
                    __half22float2(*reinterpret_cast<const __half2*>(&bw0));
                const float2 b1 =
                    __half22float2(*reinterpret_cast<const __half2*>(&bw1));
                const int px0 = wp * 32 + nt * 8 + 2 * c;
                *reinterpret_cast<float2*>(ob + (size_t)d0 * 65536 + px0) =
                    make_float2(sshrink(acc[mt][nt][0] + b0.x, th3),
                                sshrink(acc[mt][nt][1] + b0.y, th3));
                *reinterpret_cast<float2*>(ob + (size_t)(d0 + 8) * 65536 + px0) =
                    make_float2(sshrink(acc[mt][nt][2] + b1.x, th3),
                                sshrink(acc[mt][nt][3] + b1.y, th3));
            }
        }
    }
}

extern "C" void kernel_launch(void* const* d_in, const int* in_sizes, int n_in,
                              void* d_out, int out_size)
{
    (void)in_sizes; (void)n_in; (void)out_size;
    const float* x  = (const float*)d_in[0];
    const float* We = (const float*)d_in[1];
    const float* S  = (const float*)d_in[2];
    const float* th = (const float*)d_in[3];
    float* out      = (float*)d_out;

    lista_prep<<<(N_CHUNKS * WBUF_WORDS + 255) / 256, 256>>>(We, S);

    cudaFuncSetAttribute(lista_main, cudaFuncAttributeMaxDynamicSharedMemorySize,
                         SMEM_BYTES);
    lista_main<<<4096, 256, SMEM_BYTES>>>(x, th, out);
}

// round 15
// speedup vs baseline: 1.2132x; 1.1042x over previous
#include <cuda_runtime.h>
#include <cuda_fp16.h>
#include <cstdint>

typedef uint32_t u32;

// ------------------------------------------------------------------
// LISTA fused, mma.sync f16 (m16n8k16, fp32 accum), round 15.
//  = round 12 (best: 334us) with the We chunks peeled out of the main
//    loop and B-fragment loads via precomputed 32-bit smem addresses
//    (ld.shared asm) -- cuts per-chunk ALU/issue overhead.
//   B    = We @ x        (computed once, stored fp16 in smem)
//   z    = softshrink(B, th0)
//   3x:  z = softshrink(S[i] @ z + B, th[i+1])
//
// CTA = 64 px x 256 dict, 256 threads = 8 warps (4 dict x 2 px),
// warp tile 64d x 32px, 2 CTAs/SM. A (weight) fragments pre-packed in
// gmem fragment order, loaded directly gmem->registers (ld.global.nc.v4)
// with one-step-ahead register prefetch. z in smem (k-pair half2, XOR
// swizzle); B in smem fp16 per-thread order.
// ------------------------------------------------------------------

// smem u32-word map:
//   [0,    8192)  z: 128 pair-rows x 64 px (half2)
//   [8192,16384)  setup: x (32 pair-rows x 64) ; after GEMM0: B (fp16)
#define BS_OFF     8192
#define SMEM_BYTES (16384 * 4)           // 65536
#define N_CHUNKS   26                    // 2 We + 24 S, each K=32
#define WBUF_WORDS 4096

__device__ __align__(16) u32 g_wfrag[N_CHUNKS * WBUF_WORDS];

__device__ __forceinline__ u32 smem_u32(const void* p) {
    u32 a;
    asm("{ .reg .u64 t; cvta.to.shared.u64 t, %1; cvt.u32.u64 %0, t; }"
        : "=r"(a) : "l"(p));
    return a;
}
__device__ __forceinline__ float sshrink(float f, float th) {
    return f - fminf(fmaxf(f, -th), th);
}
__device__ __forceinline__ void mma16(float* c, const u32* a, u32 b0, u32 b1) {
    asm volatile(
        "mma.sync.aligned.m16n8k16.row.col.f32.f16.f16.f32 "
        "{%0,%1,%2,%3}, {%4,%5,%6,%7}, {%8,%9}, {%0,%1,%2,%3};"
        : "+f"(c[0]), "+f"(c[1]), "+f"(c[2]), "+f"(c[3])
        : "r"(a[0]), "r"(a[1]), "r"(a[2]), "r"(a[3]), "r"(b0), "r"(b1));
}
__device__ __forceinline__ void ldg4(u32* r, const u32* p) {
    asm volatile("ld.global.nc.v4.u32 {%0,%1,%2,%3}, [%4];"
                 : "=r"(r[0]), "=r"(r[1]), "=r"(r[2]), "=r"(r[3]) : "l"(p));
}
__device__ __forceinline__ u32 lds32(u32 addr) {
    u32 v;
    asm volatile("ld.shared.u32 %0, [%1];" : "=r"(v) : "r"(addr));
    return v;
}

// ------------- prep: pack We/S into fp16 a-fragment order -------------
// word layout per K=32 chunk (4096 words): [wd 2][step 1][mt 2][lane 5][reg 2]
//   d = wd*64 + mt*16 + (reg&1)*8 + (lane>>2)
//   k = step*16 + (reg>>1)*8 + (lane&3)*2  (+0,+1 packed)
// chunk order = execution order: 0,1 = We k[0:32),k[32:64); 2.. = S.
__global__ void __launch_bounds__(256, 4)
lista_prep(const float* __restrict__ We, const float* __restrict__ S)
{
    const int w = blockIdx.x * 256 + threadIdx.x;
    if (w >= N_CHUNKS * WBUF_WORDS) return;
    const int chunk = w >> 12;
    const int rem   = w & 4095;
    const int wd    = rem >> 10;
    const int step  = (rem >> 9) & 1;
    const int mt    = (rem >> 7) & 3;
    const int lane  = (rem >> 2) & 31;
    const int reg   = rem & 3;
    const int d = wd * 64 + mt * 16 + (reg & 1) * 8 + (lane >> 2);
    const int k = step * 16 + (reg >> 1) * 8 + (lane & 3) * 2;
    float v0, v1;
    if (chunk < 2) {
        v0 = We[d * 64 + chunk * 32 + k];
        v1 = We[d * 64 + chunk * 32 + k + 1];
    } else {
        const int c = chunk - 2, g = c >> 3, j = c & 7;
        v0 = S[g * 65536 + d * 256 + j * 32 + k];
        v1 = S[g * 65536 + d * 256 + j * 32 + k + 1];
    }
    __half2 h = __floats2half2_rn(v0, v1);
    g_wfrag[w] = *reinterpret_cast<u32*>(&h);
}

// one K=32 chunk: 2 steps of (A frags in regs) x (z B-frags via lds32)
//   zb0 = smem byte addr of pair-row (kpb + c), word col 0
//   a0  = step-0 frags (preloaded); a1 filled here for step 1;
//   a0 refilled with next chunk's step-0 frags unless last.
__device__ __forceinline__ void do_chunk(const u32* gwc, u32 zb0,
                                         const u32 colb[4],
                                         u32 a0[16], u32 a1[16],
                                         float acc[4][4][4], bool last)
{
#pragma unroll
    for (int mt = 0; mt < 4; mt++) ldg4(a1 + 4 * mt, gwc + 512 + mt * 128);

    // ---- step 0 ----
    {
        u32 bf[4][2];
#pragma unroll
        for (int nt = 0; nt < 4; nt++) {
            bf[nt][0] = lds32(zb0 + colb[nt]);
            bf[nt][1] = lds32(zb0 + 1024 + colb[nt]);   // +4 pair-rows
        }
#pragma unroll
        for (int mt = 0; mt < 4; mt++)
#pragma unroll
            for (int nt = 0; nt < 4; nt++)
                mma16(acc[mt][nt], a0 + 4 * mt, bf[nt][0], bf[nt][1]);
    }

    if (!last) {
#pragma unroll
        for (int mt = 0; mt < 4; mt++)
            ldg4(a0 + 4 * mt, gwc + WBUF_WORDS + mt * 128);
    }

    // ---- step 1 (pair-rows +8 -> +2048 bytes) ----
    {
        const u32 zb1 = zb0 + 2048;
        u32 bf[4][2];
#pragma unroll
        for (int nt = 0; nt < 4; nt++) {
            bf[nt][0] = lds32(zb1 + colb[nt]);
            bf[nt][1] = lds32(zb1 + 1024 + colb[nt]);
        }
#pragma unroll
        for (int mt = 0; mt < 4; mt++)
#pragma unroll
            for (int nt = 0; nt < 4; nt++)
                mma16(acc[mt][nt], a1 + 4 * mt, bf[nt][0], bf[nt][1]);
    }
}

// ---------------- main fused kernel ----------------
__global__ void __launch_bounds__(256, 2)
lista_main(const float* __restrict__ x,
           const float* __restrict__ th,
           float* __restrict__ out)
{
    extern __shared__ u32 smem[];
    u32* Zkp = smem;

    const int tid  = threadIdx.x;
    const int lane = tid & 31;
    const int wid  = tid >> 5;
    const int wd   = wid & 3;               // dict group (64 d)
    const int wp   = wid >> 2;              // pixel group (32 px), 0..1
    const int r    = lane >> 2;
    const int c    = lane & 3;

    const int pix0 = blockIdx.x * 64;
    const int b    = pix0 >> 16;            // 65536 px per image
    const int hw0  = pix0 & 65535;

    const u32 zsb = smem_u32(smem);

    const float th0 = __ldg(th + 0), th1 = __ldg(th + 1);
    const float th2 = __ldg(th + 2), th3 = __ldg(th + 3);

    // per-warp fragment base in gmem: [wd][step][mt][lane][reg]
    const u32* gw = g_wfrag + (wd * 2) * 512 + lane * 4;

    // loop-invariant B-fragment column byte-offsets
    u32 colb[4];
    {
        const int nb = wp * 32 + r;
#pragma unroll
        for (int nt = 0; nt < 4; nt++)
            colb[nt] = (u32)(nb + (((nt ^ c) & 3) << 3)) * 4;
    }
    const u32 zrow_c  = zsb + (u32)(c * 64) * 4;              // z rows
    const u32 xrow_c  = zrow_c + (u32)(BS_OFF * 4);           // x rows

    // prefetch chunk 0, step 0 fragments
    u32 a0[16], a1[16];
#pragma unroll
    for (int mt = 0; mt < 4; mt++) ldg4(a0 + 4 * mt, gw + mt * 128);

    // ---- stage x into pair-rows 0..31 of the B region (XOR swizzle) ----
    {
        const float* xb = x + (size_t)b * 64 * 65536 + hw0;
#pragma unroll
        for (int e = 0; e < 8; e++) {
            const int idx = tid + e * 256;          // 2048 = 32 prow * 64 px
            const int px  = idx & 63;
            const int pr  = idx >> 6;               // 0..31
            const float v0 = __ldg(xb + (size_t)(2 * pr) * 65536 + px);
            const float v1 = __ldg(xb + (size_t)(2 * pr + 1) * 65536 + px);
            __half2 h = __floats2half2_rn(v0, v1);
            Zkp[BS_OFF + pr * 64 + (px ^ ((pr & 3) << 3))] =
                *reinterpret_cast<u32*>(&h);
        }
    }
    __syncthreads();                        // x visible to all warps

    float acc[4][4][4];
#pragma unroll
    for (int mt = 0; mt < 4; mt++)
#pragma unroll
        for (int nt = 0; nt < 4; nt++)
#pragma unroll
            for (int q = 0; q < 4; q++) acc[mt][nt][q] = 0.0f;

    // ---- GEMM0: 2 We chunks reading x rows ----
    do_chunk(gw,              xrow_c,        colb, a0, a1, acc, false);
    do_chunk(gw + WBUF_WORDS, xrow_c + 4096, colb, a0, a1, acc, false);

    // ---- epilogue 0: B -> smem (fp16 per-thread order), z0 -> Zkp ----
    {
        __syncthreads();    // all x reads done before B overwrites region
        const bool odd = (r & 1);
#pragma unroll
        for (int mt = 0; mt < 4; mt++) {
            const int prow_lo = wd * 32 + mt * 8 + (r >> 1);
            const int prow    = odd ? (prow_lo + 4) : prow_lo;
            const int swz     = (prow & 3) << 3;
#pragma unroll
            for (int nt = 0; nt < 4; nt++) {
                __half2 hb0 = __floats2half2_rn(acc[mt][nt][0], acc[mt][nt][1]);
                __half2 hb1 = __floats2half2_rn(acc[mt][nt][2], acc[mt][nt][3]);
                const int wB = (mt * 4 + nt) * 2;
                Zkp[BS_OFF + wB * 256 + tid]       = *reinterpret_cast<u32*>(&hb0);
                Zkp[BS_OFF + (wB + 1) * 256 + tid] = *reinterpret_cast<u32*>(&hb1);
                const float s0 = sshrink(acc[mt][nt][0], th0);
                const float s1 = sshrink(acc[mt][nt][1], th0);
                const float s2 = sshrink(acc[mt][nt][2], th0);
                const float s3 = sshrink(acc[mt][nt][3], th0);
                const float o0 = __shfl_xor_sync(0xffffffffu, s0, 4);
                const float o1 = __shfl_xor_sync(0xffffffffu, s1, 4);
                const float o2 = __shfl_xor_sync(0xffffffffu, s2, 4);
                const float o3 = __shfl_xor_sync(0xffffffffu, s3, 4);
                __half2 h0, h1;
                if (!odd) { h0 = __floats2half2_rn(s0, o0);
                            h1 = __floats2half2_rn(s1, o1); }
                else      { h0 = __floats2half2_rn(o2, s2);
                            h1 = __floats2half2_rn(o3, s3); }
                const int col = (wp * 32 + nt * 8 + 2 * c) ^ swz;
                uint2 v;
                v.x = *reinterpret_cast<u32*>(&h0);
                v.y = *reinterpret_cast<u32*>(&h1);
                *reinterpret_cast<uint2*>(Zkp + prow * 64 + col) = v;
                acc[mt][nt][0] = 0.0f; acc[mt][nt][1] = 0.0f;
                acc[mt][nt][2] = 0.0f; acc[mt][nt][3] = 0.0f;
            }
        }
        __syncthreads();    // z0 / B visible before S chunks read
    }

    // ---- 24 S chunks (3 iterations x 8 chunks of K=32) ----
    const u32* gws = gw + 2 * WBUF_WORDS;
#pragma unroll 1
    for (int j = 0; j < 24; j++) {
        do_chunk(gws + (size_t)j * WBUF_WORDS,
                 zrow_c + (u32)((j & 7) << 12),    // (j&7)*16 pair-rows * 256B
                 colb, a0, a1, acc, j == 23);

        if (j == 7 || j == 15) {
            __syncthreads();    // all z reads of this iteration done
            const float theta = (j == 7) ? th1 : th2;
            const bool odd = (r & 1);
#pragma unroll
            for (int mt = 0; mt < 4; mt++) {
                const int prow_lo = wd * 32 + mt * 8 + (r >> 1);
                const int prow    = odd ? (prow_lo + 4) : prow_lo;
                const int swz     = (prow & 3) << 3;
#pragma unroll
                for (int nt = 0; nt < 4; nt++) {
                    const int wB = (mt * 4 + nt) * 2;
                    const u32 bw0 = Zkp[BS_OFF + wB * 256 + tid];
                    const u32 bw1 = Zkp[BS_OFF + (wB + 1) * 256 + tid];
                    const float2 b0 =
                        __half22float2(*reinterpret_cast<const __half2*>(&bw0));
                    const float2 b1 =
                        __half22float2(*reinterpret_cast<const __half2*>(&bw1));
                    const float s0 = sshrink(acc[mt][nt][0] + b0.x, theta);
                    const float s1 = sshrink(acc[mt][nt][1] + b0.y, theta);
                    const float s2 = sshrink(acc[mt][nt][2] + b1.x, theta);
                    const float s3 = sshrink(acc[mt][nt][3] + b1.y, theta);
                    const float o0 = __shfl_xor_sync(0xffffffffu, s0, 4);
                    const float o1 = __shfl_xor_sync(0xffffffffu, s1, 4);
                    const float o2 = __shfl_xor_sync(0xffffffffu, s2, 4);
                    const float o3 = __shfl_xor_sync(0xffffffffu, s3, 4);
                    __half2 h0, h1;
                    if (!odd) { h0 = __floats2half2_rn(s0, o0);
                                h1 = __floats2half2_rn(s1, o1); }
                    else      { h0 = __floats2half2_rn(o2, s2);
                                h1 = __floats2half2_rn(o3, s3); }
                    const int col = (wp * 32 + nt * 8 + 2 * c) ^ swz;
                    uint2 v;
                    v.x = *reinterpret_cast<u32*>(&h0);
                    v.y = *reinterpret_cast<u32*>(&h1);
                    *reinterpret_cast<uint2*>(Zkp + prow * 64 + col) = v;
                    acc[mt][nt][0] = 0.0f; acc[mt][nt][1] = 0.0f;
                    acc[mt][nt][2] = 0.0f; acc[mt][nt][3] = 0.0f;
                }
            }
            __syncthreads();    // new z visible before next chunk reads
        }
    }

    // ---- final epilogue: out = softshrink(acc + B, th3) -> gmem ----
    {
        float* ob = out + (size_t)b * 256 * 65536 + hw0;
#pragma unroll
        for (int mt = 0; mt < 4; mt++) {
            const int d0 = wd * 64 + mt * 16 + r;
#pragma unroll
            for (int nt = 0; nt < 4; nt++) {
                const int wB = (mt * 4 + nt) * 2;
                const u32 bw0 = Zkp[BS_OFF + wB * 256 + tid];
                const u32 bw1 = Zkp[BS_OFF + (wB + 1) * 256 + tid];
                const float2 b0 =
                    __half22float2(*reinterpret_cast<const __half2*>(&bw0));
                const float2 b1 =
                    __half22float2(*reinterpret_cast<const __half2*>(&bw1));
                const int px0 = wp * 32 + nt * 8 + 2 * c;
                *reinterpret_cast<float2*>(ob + (size_t)d0 * 65536 + px0) =
                    make_float2(sshrink(acc[mt][nt][0] + b0.x, th3),
                                sshrink(acc[mt][nt][1] + b0.y, th3));
                *reinterpret_cast<float2*>(ob + (size_t)(d0 + 8) * 65536 + px0) =
                    make_float2(sshrink(acc[mt][nt][2] + b1.x, th3),
                                sshrink(acc[mt][nt][3] + b1.y, th3));
            }
        }
    }
}

extern "C" void kernel_launch(void* const* d_in, const int* in_sizes, int n_in,
                              void* d_out, int out_size)
{
    (void)in_sizes; (void)n_in; (void)out_size;
    const float* x  = (const float*)d_in[0];
    const float* We = (const float*)d_in[1];
    const float* S  = (const float*)d_in[2];
    const float* th = (const float*)d_in[3];
    float* out      = (float*)d_out;

    lista_prep<<<(N_CHUNKS * WBUF_WORDS + 255) / 256, 256>>>(We, S);

    cudaFuncSetAttribute(lista_main, cudaFuncAttributeMaxDynamicSharedMemorySize,
                         SMEM_BYTES);
    lista_main<<<4096, 256, SMEM_BYTES>>>(x, th, out);
}